// round 5
// baseline (speedup 1.0000x reference)
#include <cuda_runtime.h>
#include <cuda_bf16.h>
#include <cstdint>

// MaxUnpool2D, scatter-shaped, ILP=2: one thread per PAIR of adjacent pooled
// float4 groups (32 contiguous bytes of mask + values). Each thread issues
// 4 independent loads, then writes the 2x2 output window for both groups
// (8 coalesced float4 stores). Argmax indices are unique per pooled cell,
// so every output element is written exactly once — no atomics, no init.
//
// x:    [B=8, H=128, W=128, C=64] float32
// mask: [B, H, W, C] int32 (flat idx into [HOUT*WOUT*C] per batch)
// out:  [B, 256, 256, C] float32

static constexpr int Bc   = 8;
static constexpr int Hc   = 128;
static constexpr int Wc   = 128;
static constexpr int Cc   = 64;
static constexpr int HOUT = 256;
static constexpr int WOUT = 256;
static constexpr int C4   = Cc / 4;                 // 16 float4 groups per cell
static constexpr int C8   = C4 / 2;                 // 8 pairs per cell
static constexpr int N8   = Bc * Hc * Wc * C8;      // 1,048,576 threads

__global__ __launch_bounds__(256) void max_unpool_scatter8(
    const float4* __restrict__ x4,
    const int4*   __restrict__ m4,
    float4*       __restrict__ out4)
{
    int tidx = blockIdx.x * blockDim.x + threadIdx.x;
    if (tidx >= N8) return;

    // tidx -> (b, h, w, c8); pooled float4 base = tidx*2
    int c8 = tidx & (C8 - 1);          // 8
    int t  = tidx >> 3;
    int w  = t & (Wc - 1);             // 128
    t >>= 7;
    int h  = t & (Hc - 1);             // 128
    int b  = t >> 7;

    int p0 = tidx * 2;                 // first pooled float4 group
    // Issue all 4 loads before any use (max MLP).
    int4   m0 = __ldcs(&m4[p0]);
    int4   m1 = __ldcs(&m4[p0 + 1]);
    float4 v0 = __ldcs(&x4[p0]);
    float4 v1 = __ldcs(&x4[p0 + 1]);

    int c0 = c8 << 3;                  // first scalar channel of group 0
    int ho = h << 1;
    int wo = w << 1;

    // output float4 offset of (b, ho, wo, c8*2)
    int obase = ((b * HOUT + ho) * WOUT + wo) * C4 + (c8 << 1);

#pragma unroll
    for (int dh = 0; dh < 2; ++dh) {
#pragma unroll
        for (int dw = 0; dw < 2; ++dw) {
            int flat = (((ho + dh) * WOUT) + (wo + dw)) * Cc + c0;
            float4 o0, o1;
            o0.x = (m0.x == flat    ) ? v0.x : 0.0f;
            o0.y = (m0.y == flat + 1) ? v0.y : 0.0f;
            o0.z = (m0.z == flat + 2) ? v0.z : 0.0f;
            o0.w = (m0.w == flat + 3) ? v0.w : 0.0f;
            o1.x = (m1.x == flat + 4) ? v1.x : 0.0f;
            o1.y = (m1.y == flat + 5) ? v1.y : 0.0f;
            o1.z = (m1.z == flat + 6) ? v1.z : 0.0f;
            o1.w = (m1.w == flat + 7) ? v1.w : 0.0f;
            int off = obase + dh * (WOUT * C4) + dw * C4;
            __stcs(&out4[off],     o0);
            __stcs(&out4[off + 1], o1);
        }
    }
}

extern "C" void kernel_launch(void* const* d_in, const int* in_sizes, int n_in,
                              void* d_out, int out_size)
{
    const float4* x4 = (const float4*)d_in[0];   // input_pool float32
    const int4*   m4 = (const int4*)  d_in[1];   // pool_mask int32
    float4*       o4 = (float4*)d_out;

    int threads = 256;
    int blocks  = (N8 + threads - 1) / threads;  // 4096
    max_unpool_scatter8<<<blocks, threads>>>(x4, m4, o4);
}

// round 7
// speedup vs baseline: 1.6850x; 1.6850x over previous
#include <cuda_runtime.h>
#include <cuda_bf16.h>
#include <cstdint>

// MaxUnpool2D, scatter-shaped, ILP=2 via FAR pairing: each thread handles two
// pooled float4 groups half the tensor apart (batch b and b+4). Every memory
// instruction remains one float4 per thread, warp-contiguous (full 1024B
// wavefronts) — the round-4 mistake of adjacent-pair-per-thread split every
// store into strided half-wavefronts and saturated L1.
//
// 4 independent loads + 8 independent coalesced stores per thread.
// Argmax indices are unique per pooled cell -> each output written once,
// no atomics, no zero-init pass.
//
// x:    [B=8, H=128, W=128, C=64] float32
// mask: [B, H, W, C] int32 (flat idx into [HOUT*WOUT*C] per batch)
// out:  [B, 256, 256, C] float32

static constexpr int Bc   = 8;
static constexpr int Hc   = 128;
static constexpr int Wc   = 128;
static constexpr int Cc   = 64;
static constexpr int HOUT = 256;
static constexpr int WOUT = 256;
static constexpr int C4   = Cc / 4;                  // 16
static constexpr int N4   = Bc * Hc * Wc * C4;       // 2,097,152 pooled groups
static constexpr int HALF = N4 / 2;                  // groups in batches 0..3

__global__ __launch_bounds__(256) void max_unpool_scatter_far2(
    const float4* __restrict__ x4,
    const int4*   __restrict__ m4,
    float4*       __restrict__ out4)
{
    int g0 = blockIdx.x * blockDim.x + threadIdx.x;
    if (g0 >= HALF) return;
    int g1 = g0 + HALF;

    // Issue all 4 independent loads first (max MLP).
    int4   m0 = __ldcs(&m4[g0]);
    float4 v0 = __ldcs(&x4[g0]);
    int4   m1 = __ldcs(&m4[g1]);
    float4 v1 = __ldcs(&x4[g1]);

    // Decompose g0 -> (b, h, w, c4); g1 is identical with b += 4.
    int c4 = g0 & (C4 - 1);
    int t  = g0 >> 4;
    int w  = t & (Wc - 1);
    t >>= 7;
    int h  = t & (Hc - 1);
    int b  = t >> 7;

    int c  = c4 << 2;
    int ho = h << 1;
    int wo = w << 1;

    int obase0 = ((b * HOUT + ho) * WOUT + wo) * C4 + c4;
    int obase1 = obase0 + 4 * (HOUT * WOUT * C4);     // b += 4

#pragma unroll
    for (int dh = 0; dh < 2; ++dh) {
#pragma unroll
        for (int dw = 0; dw < 2; ++dw) {
            int flat = (((ho + dh) * WOUT) + (wo + dw)) * Cc + c;
            int off  = dh * (WOUT * C4) + dw * C4;

            float4 o0;
            o0.x = (m0.x == flat    ) ? v0.x : 0.0f;
            o0.y = (m0.y == flat + 1) ? v0.y : 0.0f;
            o0.z = (m0.z == flat + 2) ? v0.z : 0.0f;
            o0.w = (m0.w == flat + 3) ? v0.w : 0.0f;
            __stcs(&out4[obase0 + off], o0);

            float4 o1;
            o1.x = (m1.x == flat    ) ? v1.x : 0.0f;
            o1.y = (m1.y == flat + 1) ? v1.y : 0.0f;
            o1.z = (m1.z == flat + 2) ? v1.z : 0.0f;
            o1.w = (m1.w == flat + 3) ? v1.w : 0.0f;
            __stcs(&out4[obase1 + off], o1);
        }
    }
}

extern "C" void kernel_launch(void* const* d_in, const int* in_sizes, int n_in,
                              void* d_out, int out_size)
{
    const float4* x4 = (const float4*)d_in[0];   // input_pool float32
    const int4*   m4 = (const int4*)  d_in[1];   // pool_mask int32
    float4*       o4 = (float4*)d_out;

    int threads = 256;
    int blocks  = (HALF + threads - 1) / threads;  // 4096
    max_unpool_scatter_far2<<<blocks, threads>>>(x4, m4, o4);
}